// round 1
// baseline (speedup 1.0000x reference)
#include <cuda_runtime.h>
#include <cstdint>

#define NUM_NODES 100000
#define HIDDEN    128
#define OFFS      2
#define MAX_E     1700000

// ---------------- device scratch (no allocation allowed) ----------------
__device__ int   g_deg[NUM_NODES];
__device__ int   g_fill[NUM_NODES];
__device__ int   g_rowptr[NUM_NODES + 1];
__device__ int   g_blksum[512];
__device__ int   g_colidx[MAX_E];
__device__ float g_dinv[NUM_NODES];
__device__ float g_bufA[(size_t)NUM_NODES * HIDDEN];
__device__ float g_bufB[(size_t)NUM_NODES * HIDDEN];

// ---------------- prep kernels ----------------
__global__ void k_zero() {
    int i = blockIdx.x * blockDim.x + threadIdx.x;
    if (i < NUM_NODES) { g_deg[i] = 0; g_fill[i] = 0; }
}

__global__ void k_count(const int* __restrict__ dst, int E) {
    int e = blockIdx.x * blockDim.x + threadIdx.x;
    if (e < E) atomicAdd(&g_deg[dst[e]], 1);
}

__global__ void k_scan_block(int n) {
    __shared__ int s[256];
    int i = blockIdx.x * 256 + threadIdx.x;
    int v = (i < n) ? g_deg[i] : 0;
    s[threadIdx.x] = v;
    __syncthreads();
    #pragma unroll
    for (int off = 1; off < 256; off <<= 1) {
        int t = (threadIdx.x >= off) ? s[threadIdx.x - off] : 0;
        __syncthreads();
        s[threadIdx.x] += t;
        __syncthreads();
    }
    if (i < n) g_rowptr[i] = s[threadIdx.x] - v;   // exclusive
    if (threadIdx.x == 255) g_blksum[blockIdx.x] = s[255];
}

__global__ void k_scan_top(int nblk) {
    __shared__ int s[512];
    int v = (threadIdx.x < nblk) ? g_blksum[threadIdx.x] : 0;
    s[threadIdx.x] = v;
    __syncthreads();
    #pragma unroll
    for (int off = 1; off < 512; off <<= 1) {
        int t = (threadIdx.x >= off) ? s[threadIdx.x - off] : 0;
        __syncthreads();
        s[threadIdx.x] += t;
        __syncthreads();
    }
    g_blksum[threadIdx.x] = s[threadIdx.x] - v;    // exclusive
}

__global__ void k_scan_add(int n, int E) {
    int i = blockIdx.x * 256 + threadIdx.x;
    if (i < n) g_rowptr[i] += g_blksum[blockIdx.x];
    if (i == 0) g_rowptr[n] = E;
}

__global__ void k_dinv() {
    int i = blockIdx.x * blockDim.x + threadIdx.x;
    if (i < NUM_NODES) g_dinv[i] = rsqrtf((float)(g_deg[i] + 1)); // +1 self loop
}

__global__ void k_fill(const int* __restrict__ src, const int* __restrict__ dst, int E) {
    int e = blockIdx.x * blockDim.x + threadIdx.x;
    if (e < E) {
        int d = dst[e];
        int p = g_rowptr[d] + atomicAdd(&g_fill[d], 1);
        g_colidx[p] = src[e];
    }
}

// ---------------- normalized aggregation: one warp per dst node ----------------
__global__ __launch_bounds__(256)
void k_agg(const float* __restrict__ x, float* __restrict__ out, int n) {
    int gw   = (blockIdx.x * blockDim.x + threadIdx.x) >> 5;
    int lane = threadIdx.x & 31;
    if (gw >= n) return;
    float dv = g_dinv[gw];
    const float4* xr = reinterpret_cast<const float4*>(x);
    float4 a  = xr[(size_t)gw * 32 + lane];
    float  ws = dv * dv;                       // self-loop weight
    float4 acc = make_float4(a.x * ws, a.y * ws, a.z * ws, a.w * ws);
    int b = g_rowptr[gw], e = g_rowptr[gw + 1];
    int j = b;
    for (; j + 2 <= e; j += 2) {
        int   s0 = g_colidx[j],     s1 = g_colidx[j + 1];
        float w0 = g_dinv[s0] * dv, w1 = g_dinv[s1] * dv;
        float4 v0 = xr[(size_t)s0 * 32 + lane];
        float4 v1 = xr[(size_t)s1 * 32 + lane];
        acc.x += v0.x * w0 + v1.x * w1;
        acc.y += v0.y * w0 + v1.y * w1;
        acc.z += v0.z * w0 + v1.z * w1;
        acc.w += v0.w * w0 + v1.w * w1;
    }
    if (j < e) {
        int   s0 = g_colidx[j];
        float w0 = g_dinv[s0] * dv;
        float4 v0 = xr[(size_t)s0 * 32 + lane];
        acc.x += v0.x * w0; acc.y += v0.y * w0;
        acc.z += v0.z * w0; acc.w += v0.w * w0;
    }
    reinterpret_cast<float4*>(out)[(size_t)gw * 32 + lane] = acc;
}

// ---------------- fp32 tiled GEMM: C[M,128] = A[M,128] @ W[128,128] + bias ----------------
template <bool RELU>
__global__ __launch_bounds__(256)
void k_gemm(const float* __restrict__ A, float* __restrict__ C,
            const float* __restrict__ W, const float* __restrict__ bias, int M) {
    __shared__ __align__(16) float As[16][68];   // [k][m], padded
    __shared__ __align__(16) float Bs[16][128];  // [k][n]
    int tid = threadIdx.x;
    int tx  = tid & 31;            // 32 col-threads, 4 cols each
    int ty  = tid >> 5;            // 8 row-threads, 8 rows each
    int brow = blockIdx.x * 64;
    int a_row = tid >> 2;          // 0..63
    int a_col = (tid & 3) << 2;    // 0,4,8,12

    float acc[8][4];
    #pragma unroll
    for (int i = 0; i < 8; i++)
        #pragma unroll
        for (int jj = 0; jj < 4; jj++) acc[i][jj] = 0.0f;

    for (int k0 = 0; k0 < 128; k0 += 16) {
        int gr = brow + a_row;
        float4 av = make_float4(0.f, 0.f, 0.f, 0.f);
        if (gr < M)
            av = *reinterpret_cast<const float4*>(A + (size_t)gr * 128 + k0 + a_col);
        As[a_col + 0][a_row] = av.x;
        As[a_col + 1][a_row] = av.y;
        As[a_col + 2][a_row] = av.z;
        As[a_col + 3][a_row] = av.w;
        #pragma unroll
        for (int i = 0; i < 2; i++) {
            int idx = tid + i * 256;
            int br  = idx >> 5;
            int bc  = (idx & 31) << 2;
            *reinterpret_cast<float4*>(&Bs[br][bc]) =
                *reinterpret_cast<const float4*>(W + (size_t)(k0 + br) * 128 + bc);
        }
        __syncthreads();
        #pragma unroll
        for (int kk = 0; kk < 16; kk++) {
            float4 a0 = *reinterpret_cast<const float4*>(&As[kk][ty * 8]);
            float4 a1 = *reinterpret_cast<const float4*>(&As[kk][ty * 8 + 4]);
            float4 b  = *reinterpret_cast<const float4*>(&Bs[kk][tx * 4]);
            float a[8] = {a0.x, a0.y, a0.z, a0.w, a1.x, a1.y, a1.z, a1.w};
            #pragma unroll
            for (int i = 0; i < 8; i++) {
                acc[i][0] += a[i] * b.x;
                acc[i][1] += a[i] * b.y;
                acc[i][2] += a[i] * b.z;
                acc[i][3] += a[i] * b.w;
            }
        }
        __syncthreads();
    }

    float4 bv = *reinterpret_cast<const float4*>(bias + tx * 4);
    #pragma unroll
    for (int i = 0; i < 8; i++) {
        int row = brow + ty * 8 + i;
        if (row < M) {
            float4 o;
            o.x = acc[i][0] + bv.x;
            o.y = acc[i][1] + bv.y;
            o.z = acc[i][2] + bv.z;
            o.w = acc[i][3] + bv.w;
            if (RELU) {
                o.x = fmaxf(o.x, 0.f); o.y = fmaxf(o.y, 0.f);
                o.z = fmaxf(o.z, 0.f); o.w = fmaxf(o.w, 0.f);
            }
            *reinterpret_cast<float4*>(C + (size_t)row * 128 + tx * 4) = o;
        }
    }
}

// ---------------- final gather: one warp per seq position ----------------
__global__ __launch_bounds__(256)
void k_gather(const float* __restrict__ z, const float* __restrict__ emb,
              const int* __restrict__ seq, float* __restrict__ out, int S) {
    int t = blockIdx.x * blockDim.x + threadIdx.x;
    int pos = t >> 5, lane = t & 31;
    if (pos >= S) return;
    int v = seq[pos];
    const float4* srcp;
    size_t row;
    if (v >= 0) { srcp = reinterpret_cast<const float4*>(z);   row = (size_t)v; }
    else        { srcp = reinterpret_cast<const float4*>(emb); row = (size_t)(v + OFFS + NUM_NODES); }
    reinterpret_cast<float4*>(out)[(size_t)pos * 32 + lane] = srcp[row * 32 + lane];
}

// ---------------- host launch ----------------
extern "C" void kernel_launch(void* const* d_in, const int* in_sizes, int n_in,
                              void* d_out, int out_size) {
    const float* emb = (const float*)d_in[0];
    const float* W0  = (const float*)d_in[1];
    const float* b0  = (const float*)d_in[2];
    const float* W1  = (const float*)d_in[3];
    const float* b1  = (const float*)d_in[4];
    const int*   ei  = (const int*)d_in[5];
    const int*   seq = (const int*)d_in[6];

    int E = in_sizes[5] / 2;
    int S = in_sizes[6];
    const int* src = ei;
    const int* dst = ei + E;

    float *bufA = nullptr, *bufB = nullptr;
    cudaGetSymbolAddress((void**)&bufA, g_bufA);
    cudaGetSymbolAddress((void**)&bufB, g_bufB);

    const int NBLK = (NUM_NODES + 255) / 256;

    // graph prep: degrees -> CSR
    k_zero<<<NBLK, 256>>>();
    k_count<<<(E + 255) / 256, 256>>>(dst, E);
    k_scan_block<<<NBLK, 256>>>(NUM_NODES);
    k_scan_top<<<1, 512>>>(NBLK);
    k_scan_add<<<NBLK, 256>>>(NUM_NODES, E);
    k_dinv<<<NBLK, 256>>>();
    k_fill<<<(E + 255) / 256, 256>>>(src, dst, E);

    const int AGG_GRID = (NUM_NODES * 32 + 255) / 256;
    const int GEMM_GRID = (NUM_NODES + 63) / 64;

    // layer 1: bufA = agg(emb) ; bufB = relu(bufA @ W0 + b0)
    k_agg<<<AGG_GRID, 256>>>(emb, bufA, NUM_NODES);
    k_gemm<true><<<GEMM_GRID, 256>>>(bufA, bufB, W0, b0, NUM_NODES);

    // layer 2: bufA = agg(bufB) ; bufB = bufA @ W1 + b1  (z)
    k_agg<<<AGG_GRID, 256>>>(bufB, bufA, NUM_NODES);
    k_gemm<false><<<GEMM_GRID, 256>>>(bufA, bufB, W1, b1, NUM_NODES);

    // gather
    k_gather<<<(S * 32 + 255) / 256, 256>>>(bufB, emb, seq, (float*)d_out, S);
}

// round 3
// speedup vs baseline: 1.0880x; 1.0880x over previous
#include <cuda_runtime.h>
#include <cuda_bf16.h>
#include <cstdint>

#define NUM_NODES 100000
#define HIDDEN    128
#define OFFS      2
#define MAX_E     1700000

// ---------------- device scratch ----------------
__device__ int   g_deg[NUM_NODES];
__device__ int   g_fill[NUM_NODES];
__device__ int   g_rowptr[NUM_NODES + 1];
__device__ int   g_blksum[512];
__device__ int   g_colidx[MAX_E];
__device__ float g_dinv[NUM_NODES];
__device__ float g_h[(size_t)NUM_NODES * HIDDEN];          // layer1 out, reused for z
__device__ __nv_bfloat16 g_xh[(size_t)NUM_NODES * HIDDEN]; // agg hi
__device__ __nv_bfloat16 g_xl[(size_t)NUM_NODES * HIDDEN]; // agg lo
__device__ __nv_bfloat16 g_w0h[HIDDEN * HIDDEN];           // W0^T hi  [n][k]
__device__ __nv_bfloat16 g_w0l[HIDDEN * HIDDEN];
__device__ __nv_bfloat16 g_w1h[HIDDEN * HIDDEN];
__device__ __nv_bfloat16 g_w1l[HIDDEN * HIDDEN];

// ---------------- helpers ----------------
__device__ __forceinline__ uint32_t smem_u32(const void* p) {
    uint32_t a;
    asm("{ .reg .u64 t; cvta.to.shared.u64 t, %1; cvt.u32.u64 %0, t; }" : "=r"(a) : "l"(p));
    return a;
}
__device__ __forceinline__ void ldsm_x4(uint32_t addr, uint32_t& r0, uint32_t& r1,
                                        uint32_t& r2, uint32_t& r3) {
    asm volatile("ldmatrix.sync.aligned.m8n8.x4.shared.b16 {%0,%1,%2,%3}, [%4];"
                 : "=r"(r0), "=r"(r1), "=r"(r2), "=r"(r3) : "r"(addr));
}
__device__ __forceinline__ void mma_bf16(float* c, const uint32_t* a, uint32_t b0, uint32_t b1) {
    asm volatile(
        "mma.sync.aligned.m16n8k16.row.col.f32.bf16.bf16.f32 "
        "{%0,%1,%2,%3}, {%4,%5,%6,%7}, {%8,%9}, {%0,%1,%2,%3};"
        : "+f"(c[0]), "+f"(c[1]), "+f"(c[2]), "+f"(c[3])
        : "r"(a[0]), "r"(a[1]), "r"(a[2]), "r"(a[3]), "r"(b0), "r"(b1));
}

// ---------------- prep kernels ----------------
__global__ void k_init(const float* __restrict__ W0, const float* __restrict__ W1) {
    int i = blockIdx.x * 256 + threadIdx.x;
    if (i < NUM_NODES) { g_deg[i] = 0; g_fill[i] = 0; }
    if (blockIdx.x < 128) {
        int idx = (blockIdx.x & 63) * 256 + threadIdx.x;   // 0..16383 = k*128+n
        const float* W = (blockIdx.x < 64) ? W0 : W1;
        __nv_bfloat16* Th = (blockIdx.x < 64) ? g_w0h : g_w1h;
        __nv_bfloat16* Tl = (blockIdx.x < 64) ? g_w0l : g_w1l;
        int k = idx >> 7, n = idx & 127;
        float w = W[idx];
        __nv_bfloat16 h = __float2bfloat16(w);
        Th[n * 128 + k] = h;
        Tl[n * 128 + k] = __float2bfloat16(w - __bfloat162float(h));
    }
}

__global__ void k_count(const int* __restrict__ dst, int E) {
    int e = blockIdx.x * blockDim.x + threadIdx.x;
    if (e < E) atomicAdd(&g_deg[dst[e]], 1);
}

__global__ void k_scan_block(int n) {
    __shared__ int s[256];
    int i = blockIdx.x * 256 + threadIdx.x;
    int v = (i < n) ? g_deg[i] : 0;
    s[threadIdx.x] = v;
    __syncthreads();
    #pragma unroll
    for (int off = 1; off < 256; off <<= 1) {
        int t = (threadIdx.x >= off) ? s[threadIdx.x - off] : 0;
        __syncthreads();
        s[threadIdx.x] += t;
        __syncthreads();
    }
    if (i < n) g_rowptr[i] = s[threadIdx.x] - v;
    if (threadIdx.x == 255) g_blksum[blockIdx.x] = s[255];
}

__global__ void k_scan_top(int nblk) {
    __shared__ int s[512];
    int v = (threadIdx.x < nblk) ? g_blksum[threadIdx.x] : 0;
    s[threadIdx.x] = v;
    __syncthreads();
    #pragma unroll
    for (int off = 1; off < 512; off <<= 1) {
        int t = (threadIdx.x >= off) ? s[threadIdx.x - off] : 0;
        __syncthreads();
        s[threadIdx.x] += t;
        __syncthreads();
    }
    g_blksum[threadIdx.x] = s[threadIdx.x] - v;
}

__global__ void k_scan_add(int n, int E) {
    int i = blockIdx.x * 256 + threadIdx.x;
    if (i < n) {
        g_rowptr[i] += g_blksum[blockIdx.x];
        g_dinv[i] = rsqrtf((float)(g_deg[i] + 1));  // +1 self loop
    }
    if (i == 0) g_rowptr[n] = E;
}

__global__ void k_fill(const int* __restrict__ src, const int* __restrict__ dst, int E) {
    int e = blockIdx.x * blockDim.x + threadIdx.x;
    if (e < E) {
        int d = dst[e];
        int p = g_rowptr[d] + atomicAdd(&g_fill[d], 1);
        g_colidx[p] = src[e];
    }
}

// ---------------- aggregation: one warp per dst node, emits bf16 hi/lo ----------------
__global__ __launch_bounds__(256)
void k_agg(const float* __restrict__ x, __nv_bfloat16* __restrict__ oh,
           __nv_bfloat16* __restrict__ ol, int n) {
    int gw   = (blockIdx.x * blockDim.x + threadIdx.x) >> 5;
    int lane = threadIdx.x & 31;
    if (gw >= n) return;
    float dv = g_dinv[gw];
    const float4* xr = reinterpret_cast<const float4*>(x);
    float4 a  = xr[(size_t)gw * 32 + lane];
    float  ws = dv * dv;
    float4 acc = make_float4(a.x * ws, a.y * ws, a.z * ws, a.w * ws);
    int b = g_rowptr[gw], e = g_rowptr[gw + 1];
    int j = b;
    for (; j + 2 <= e; j += 2) {
        int   s0 = g_colidx[j],     s1 = g_colidx[j + 1];
        float w0 = g_dinv[s0] * dv, w1 = g_dinv[s1] * dv;
        float4 v0 = xr[(size_t)s0 * 32 + lane];
        float4 v1 = xr[(size_t)s1 * 32 + lane];
        acc.x += v0.x * w0 + v1.x * w1;
        acc.y += v0.y * w0 + v1.y * w1;
        acc.z += v0.z * w0 + v1.z * w1;
        acc.w += v0.w * w0 + v1.w * w1;
    }
    if (j < e) {
        int   s0 = g_colidx[j];
        float w0 = g_dinv[s0] * dv;
        float4 v0 = xr[(size_t)s0 * 32 + lane];
        acc.x += v0.x * w0; acc.y += v0.y * w0;
        acc.z += v0.z * w0; acc.w += v0.w * w0;
    }
    float v[4] = {acc.x, acc.y, acc.z, acc.w};
    ushort4 sh, sl;
    unsigned short* ph = &sh.x;
    unsigned short* pl = &sl.x;
    #pragma unroll
    for (int c = 0; c < 4; c++) {
        __nv_bfloat16 hh = __float2bfloat16(v[c]);
        __nv_bfloat16 ll = __float2bfloat16(v[c] - __bfloat162float(hh));
        ph[c] = __bfloat16_as_ushort(hh);
        pl[c] = __bfloat16_as_ushort(ll);
    }
    size_t base = (size_t)gw * 128 + lane * 4;
    *reinterpret_cast<ushort4*>(oh + base) = sh;
    *reinterpret_cast<ushort4*>(ol + base) = sl;
}

// ---------------- bf16x3 tensor-core GEMM via mma.sync ----------------
// C[M,128] = (Ah+Al) @ (Wh+Wl) + bias  (3 passes: Ah*Wh + Al*Wh + Ah*Wl)
// smem: Ah, Al [row][k] and Bh, Bl = W^T [n][k], padded stride 136 bf16.
#define LDS_STRIDE 136
#define TILE_HALFS (128 * LDS_STRIDE)
#define GEMM_SMEM  (4 * TILE_HALFS * 2)

template <bool RELU>
__global__ __launch_bounds__(256)
void k_gemm_mma(const __nv_bfloat16* __restrict__ Ah, const __nv_bfloat16* __restrict__ Al,
                const __nv_bfloat16* __restrict__ Bh, const __nv_bfloat16* __restrict__ Bl,
                const float* __restrict__ bias, float* __restrict__ C, int M) {
    extern __shared__ __align__(16) __nv_bfloat16 sm[];
    __nv_bfloat16* sAh = sm;
    __nv_bfloat16* sAl = sAh + TILE_HALFS;
    __nv_bfloat16* sBh = sAl + TILE_HALFS;
    __nv_bfloat16* sBl = sBh + TILE_HALFS;

    const int tid = threadIdx.x, wid = tid >> 5, lane = tid & 31;
    const int brow = blockIdx.x * 128;

    // cooperative load: 128 rows x 128 cols per tile, uint4 = 8 bf16
    for (int i = tid; i < 2048; i += 256) {
        int r  = i >> 4;
        int c8 = (i & 15) << 3;
        int d  = r * LDS_STRIDE + c8;
        int grow = brow + r;
        uint4 va = make_uint4(0, 0, 0, 0), vl = make_uint4(0, 0, 0, 0);
        if (grow < M) {
            va = *reinterpret_cast<const uint4*>(Ah + (size_t)grow * 128 + c8);
            vl = *reinterpret_cast<const uint4*>(Al + (size_t)grow * 128 + c8);
        }
        *reinterpret_cast<uint4*>(sAh + d) = va;
        *reinterpret_cast<uint4*>(sAl + d) = vl;
        *reinterpret_cast<uint4*>(sBh + d) =
            *reinterpret_cast<const uint4*>(Bh + (size_t)r * 128 + c8);
        *reinterpret_cast<uint4*>(sBl + d) =
            *reinterpret_cast<const uint4*>(Bl + (size_t)r * 128 + c8);
    }
    __syncthreads();

    // warp tiling: 4 warps along M (32 rows each), 2 along N (64 cols each)
    const int mb = (wid & 3) * 32;
    const int nb = (wid >> 2) * 64;

    float acc[2][8][4];
    #pragma unroll
    for (int i = 0; i < 2; i++)
        #pragma unroll
        for (int j = 0; j < 8; j++)
            #pragma unroll
            for (int q = 0; q < 4; q++) acc[i][j][q] = 0.0f;

    // ldmatrix lane addressing: rows (lane&15), byte-col (lane>>4)*16
    const int lrow  = lane & 15;
    const int lbyte = (lane >> 4) << 4;

    #pragma unroll
    for (int pass = 0; pass < 3; pass++) {
        const __nv_bfloat16* pA = (pass == 1) ? sAl : sAh;
        const __nv_bfloat16* pB = (pass == 2) ? sBl : sBh;
        #pragma unroll
        for (int k16 = 0; k16 < 8; k16++) {
            int kb = k16 * 16;
            uint32_t a[2][4];
            #pragma unroll
            for (int i = 0; i < 2; i++) {
                uint32_t ad = smem_u32(pA + (mb + i * 16 + lrow) * LDS_STRIDE + kb) + lbyte;
                ldsm_x4(ad, a[i][0], a[i][1], a[i][2], a[i][3]);
            }
            uint32_t b[4][4];   // b[j]: {n8tile0.b0, n8tile1.b0, n8tile0.b1, n8tile1.b1}
            #pragma unroll
            for (int j = 0; j < 4; j++) {
                uint32_t ad = smem_u32(pB + (nb + j * 16 + lrow) * LDS_STRIDE + kb) + lbyte;
                ldsm_x4(ad, b[j][0], b[j][1], b[j][2], b[j][3]);
            }
            #pragma unroll
            for (int i = 0; i < 2; i++)
                #pragma unroll
                for (int j = 0; j < 4; j++) {
                    mma_bf16(acc[i][j * 2 + 0], a[i], b[j][0], b[j][2]);
                    mma_bf16(acc[i][j * 2 + 1], a[i], b[j][1], b[j][3]);
                }
        }
    }

    // epilogue: c frag: (row = t/4 [+8], col = (t%4)*2 [,+1])
    const int tr = lane >> 2, tc = (lane & 3) * 2;
    #pragma unroll
    for (int i = 0; i < 2; i++) {
        #pragma unroll
        for (int j = 0; j < 8; j++) {
            int col = nb + j * 8 + tc;
            float bx = bias[col], by = bias[col + 1];
            int row0 = brow + mb + i * 16 + tr;
            float2 o0, o1;
            o0.x = acc[i][j][0] + bx; o0.y = acc[i][j][1] + by;
            o1.x = acc[i][j][2] + bx; o1.y = acc[i][j][3] + by;
            if (RELU) {
                o0.x = fmaxf(o0.x, 0.f); o0.y = fmaxf(o0.y, 0.f);
                o1.x = fmaxf(o1.x, 0.f); o1.y = fmaxf(o1.y, 0.f);
            }
            if (row0 < M)
                *reinterpret_cast<float2*>(C + (size_t)row0 * 128 + col) = o0;
            if (row0 + 8 < M)
                *reinterpret_cast<float2*>(C + (size_t)(row0 + 8) * 128 + col) = o1;
        }
    }
}

// ---------------- final gather ----------------
__global__ __launch_bounds__(256)
void k_gather(const float* __restrict__ z, const float* __restrict__ emb,
              const int* __restrict__ seq, float* __restrict__ out, int S) {
    int t = blockIdx.x * blockDim.x + threadIdx.x;
    int pos = t >> 5, lane = t & 31;
    if (pos >= S) return;
    int v = seq[pos];
    const float4* srcp;
    size_t row;
    if (v >= 0) { srcp = reinterpret_cast<const float4*>(z);   row = (size_t)v; }
    else        { srcp = reinterpret_cast<const float4*>(emb); row = (size_t)(v + OFFS + NUM_NODES); }
    reinterpret_cast<float4*>(out)[(size_t)pos * 32 + lane] = srcp[row * 32 + lane];
}

// ---------------- host launch ----------------
extern "C" void kernel_launch(void* const* d_in, const int* in_sizes, int n_in,
                              void* d_out, int out_size) {
    const float* emb = (const float*)d_in[0];
    const float* W0  = (const float*)d_in[1];
    const float* b0  = (const float*)d_in[2];
    const float* W1  = (const float*)d_in[3];
    const float* b1  = (const float*)d_in[4];
    const int*   ei  = (const int*)d_in[5];
    const int*   seq = (const int*)d_in[6];

    int E = in_sizes[5] / 2;
    int S = in_sizes[6];
    const int* src = ei;
    const int* dst = ei + E;

    float *h = nullptr;
    __nv_bfloat16 *xh = nullptr, *xl = nullptr, *w0h = nullptr, *w0l = nullptr,
                  *w1h = nullptr, *w1l = nullptr;
    cudaGetSymbolAddress((void**)&h,   g_h);
    cudaGetSymbolAddress((void**)&xh,  g_xh);
    cudaGetSymbolAddress((void**)&xl,  g_xl);
    cudaGetSymbolAddress((void**)&w0h, g_w0h);
    cudaGetSymbolAddress((void**)&w0l, g_w0l);
    cudaGetSymbolAddress((void**)&w1h, g_w1h);
    cudaGetSymbolAddress((void**)&w1l, g_w1l);

    cudaFuncSetAttribute(k_gemm_mma<true>,  cudaFuncAttributeMaxDynamicSharedMemorySize, GEMM_SMEM);
    cudaFuncSetAttribute(k_gemm_mma<false>, cudaFuncAttributeMaxDynamicSharedMemorySize, GEMM_SMEM);

    const int NBLK = (NUM_NODES + 255) / 256;

    k_init<<<NBLK, 256>>>(W0, W1);
    k_count<<<(E + 255) / 256, 256>>>(dst, E);
    k_scan_block<<<NBLK, 256>>>(NUM_NODES);
    k_scan_top<<<1, 512>>>(NBLK);
    k_scan_add<<<NBLK, 256>>>(NUM_NODES, E);
    k_fill<<<(E + 255) / 256, 256>>>(src, dst, E);

    const int AGG_GRID  = (NUM_NODES * 32 + 255) / 256;
    const int GEMM_GRID = (NUM_NODES + 127) / 128;

    // layer 1
    k_agg<<<AGG_GRID, 256>>>(emb, xh, xl, NUM_NODES);
    k_gemm_mma<true><<<GEMM_GRID, 256, GEMM_SMEM>>>(xh, xl, w0h, w0l, b0, h, NUM_NODES);
    // layer 2
    k_agg<<<AGG_GRID, 256>>>(h, xh, xl, NUM_NODES);
    k_gemm_mma<false><<<GEMM_GRID, 256, GEMM_SMEM>>>(xh, xl, w1h, w1l, b1, h, NUM_NODES);
    // gather
    k_gather<<<(S * 32 + 255) / 256, 256>>>(h, emb, seq, (float*)d_out, S);
}

// round 4
// speedup vs baseline: 1.4713x; 1.3524x over previous
#include <cuda_runtime.h>
#include <cuda_bf16.h>
#include <cstdint>

#define NUM_NODES 100000
#define HIDDEN    128
#define OFFS      2
#define MAX_E     1700000
#define MAX_SEQ   32768

// ---------------- device scratch ----------------
__device__ int   g_deg[NUM_NODES];
__device__ int   g_fill[NUM_NODES];
__device__ int   g_rowptr[NUM_NODES + 1];
__device__ int   g_blksum[512];
__device__ int   g_colidx[MAX_E];
__device__ float g_dinv[NUM_NODES];
__device__ int   g_need[NUM_NODES];     // 1 if node appears in seq
__device__ int   g_slot[NUM_NODES];     // node -> compact slot
__device__ int   g_list[MAX_SEQ];       // slot -> node
__device__ int   g_cnt;                 // number of needed nodes
__device__ float g_h[(size_t)NUM_NODES * HIDDEN];          // layer1 output
__device__ float g_z[(size_t)MAX_SEQ * HIDDEN];            // layer2 compact output
__device__ __nv_bfloat16 g_xh[(size_t)NUM_NODES * HIDDEN]; // agg hi
__device__ __nv_bfloat16 g_xl[(size_t)NUM_NODES * HIDDEN]; // agg lo
__device__ __nv_bfloat16 g_w0h[HIDDEN * HIDDEN];           // W0^T hi  [n][k]
__device__ __nv_bfloat16 g_w0l[HIDDEN * HIDDEN];
__device__ __nv_bfloat16 g_w1h[HIDDEN * HIDDEN];
__device__ __nv_bfloat16 g_w1l[HIDDEN * HIDDEN];

// ---------------- helpers ----------------
__device__ __forceinline__ uint32_t smem_u32(const void* p) {
    uint32_t a;
    asm("{ .reg .u64 t; cvta.to.shared.u64 t, %1; cvt.u32.u64 %0, t; }" : "=r"(a) : "l"(p));
    return a;
}
__device__ __forceinline__ void ldsm_x4(uint32_t addr, uint32_t& r0, uint32_t& r1,
                                        uint32_t& r2, uint32_t& r3) {
    asm volatile("ldmatrix.sync.aligned.m8n8.x4.shared.b16 {%0,%1,%2,%3}, [%4];"
                 : "=r"(r0), "=r"(r1), "=r"(r2), "=r"(r3) : "r"(addr));
}
__device__ __forceinline__ void mma_bf16(float* c, const uint32_t* a, uint32_t b0, uint32_t b1) {
    asm volatile(
        "mma.sync.aligned.m16n8k16.row.col.f32.bf16.bf16.f32 "
        "{%0,%1,%2,%3}, {%4,%5,%6,%7}, {%8,%9}, {%0,%1,%2,%3};"
        : "+f"(c[0]), "+f"(c[1]), "+f"(c[2]), "+f"(c[3])
        : "r"(a[0]), "r"(a[1]), "r"(a[2]), "r"(a[3]), "r"(b0), "r"(b1));
}

// ---------------- prep kernels ----------------
__global__ void k_init(const float* __restrict__ W0, const float* __restrict__ W1) {
    int i = blockIdx.x * 256 + threadIdx.x;
    if (i < NUM_NODES) { g_deg[i] = 0; g_fill[i] = 0; g_need[i] = 0; }
    if (i == 0) g_cnt = 0;
    if (blockIdx.x < 128) {
        int idx = (blockIdx.x & 63) * 256 + threadIdx.x;   // 0..16383 = k*128+n
        const float* W = (blockIdx.x < 64) ? W0 : W1;
        __nv_bfloat16* Th = (blockIdx.x < 64) ? g_w0h : g_w1h;
        __nv_bfloat16* Tl = (blockIdx.x < 64) ? g_w0l : g_w1l;
        int k = idx >> 7, n = idx & 127;
        float w = W[idx];
        __nv_bfloat16 h = __float2bfloat16(w);
        Th[n * 128 + k] = h;
        Tl[n * 128 + k] = __float2bfloat16(w - __bfloat162float(h));
    }
}

__global__ void k_mark(const int* __restrict__ seq, int S) {
    int i = blockIdx.x * 256 + threadIdx.x;
    if (i < S) {
        int v = seq[i];
        if (v >= 0) g_need[v] = 1;
    }
}

__global__ void k_build() {
    int i = blockIdx.x * 256 + threadIdx.x;
    if (i < NUM_NODES && g_need[i]) {
        int s = atomicAdd(&g_cnt, 1);
        g_slot[i] = s;
        g_list[s] = i;
    }
}

__global__ void k_count(const int* __restrict__ dst, int E) {
    int e = blockIdx.x * blockDim.x + threadIdx.x;
    if (e < E) atomicAdd(&g_deg[dst[e]], 1);
}

__global__ void k_scan_block(int n) {
    __shared__ int s[256];
    int i = blockIdx.x * 256 + threadIdx.x;
    int v = (i < n) ? g_deg[i] : 0;
    s[threadIdx.x] = v;
    __syncthreads();
    #pragma unroll
    for (int off = 1; off < 256; off <<= 1) {
        int t = (threadIdx.x >= off) ? s[threadIdx.x - off] : 0;
        __syncthreads();
        s[threadIdx.x] += t;
        __syncthreads();
    }
    if (i < n) g_rowptr[i] = s[threadIdx.x] - v;
    if (threadIdx.x == 255) g_blksum[blockIdx.x] = s[255];
}

__global__ void k_scan_top(int nblk) {
    __shared__ int s[512];
    int v = (threadIdx.x < nblk) ? g_blksum[threadIdx.x] : 0;
    s[threadIdx.x] = v;
    __syncthreads();
    #pragma unroll
    for (int off = 1; off < 512; off <<= 1) {
        int t = (threadIdx.x >= off) ? s[threadIdx.x - off] : 0;
        __syncthreads();
        s[threadIdx.x] += t;
        __syncthreads();
    }
    g_blksum[threadIdx.x] = s[threadIdx.x] - v;
}

__global__ void k_scan_add(int n, int E) {
    int i = blockIdx.x * 256 + threadIdx.x;
    if (i < n) {
        g_rowptr[i] += g_blksum[blockIdx.x];
        g_dinv[i] = rsqrtf((float)(g_deg[i] + 1));  // +1 self loop
    }
    if (i == 0) g_rowptr[n] = E;
}

__global__ void k_fill(const int* __restrict__ src, const int* __restrict__ dst, int E) {
    int e = blockIdx.x * blockDim.x + threadIdx.x;
    if (e < E) {
        int d = dst[e];
        int p = g_rowptr[d] + atomicAdd(&g_fill[d], 1);
        g_colidx[p] = src[e];
    }
}

// ---------------- aggregation core ----------------
__device__ __forceinline__ void agg_node(const float4* __restrict__ xr, int node, int lane,
                                         __nv_bfloat16* __restrict__ oh,
                                         __nv_bfloat16* __restrict__ ol, int orow) {
    float dv = g_dinv[node];
    float4 a  = xr[(size_t)node * 32 + lane];
    float  ws = dv * dv;
    float4 acc = make_float4(a.x * ws, a.y * ws, a.z * ws, a.w * ws);
    int b = g_rowptr[node], e = g_rowptr[node + 1];
    int j = b;
    for (; j + 4 <= e; j += 4) {
        int s0 = g_colidx[j], s1 = g_colidx[j + 1], s2 = g_colidx[j + 2], s3 = g_colidx[j + 3];
        float w0 = g_dinv[s0] * dv, w1 = g_dinv[s1] * dv;
        float w2 = g_dinv[s2] * dv, w3 = g_dinv[s3] * dv;
        float4 v0 = xr[(size_t)s0 * 32 + lane];
        float4 v1 = xr[(size_t)s1 * 32 + lane];
        float4 v2 = xr[(size_t)s2 * 32 + lane];
        float4 v3 = xr[(size_t)s3 * 32 + lane];
        acc.x += v0.x * w0 + v1.x * w1 + v2.x * w2 + v3.x * w3;
        acc.y += v0.y * w0 + v1.y * w1 + v2.y * w2 + v3.y * w3;
        acc.z += v0.z * w0 + v1.z * w1 + v2.z * w2 + v3.z * w3;
        acc.w += v0.w * w0 + v1.w * w1 + v2.w * w2 + v3.w * w3;
    }
    for (; j < e; j++) {
        int   s0 = g_colidx[j];
        float w0 = g_dinv[s0] * dv;
        float4 v0 = xr[(size_t)s0 * 32 + lane];
        acc.x += v0.x * w0; acc.y += v0.y * w0;
        acc.z += v0.z * w0; acc.w += v0.w * w0;
    }
    float v[4] = {acc.x, acc.y, acc.z, acc.w};
    ushort4 sh, sl;
    unsigned short* ph = &sh.x;
    unsigned short* pl = &sl.x;
    #pragma unroll
    for (int c = 0; c < 4; c++) {
        __nv_bfloat16 hh = __float2bfloat16(v[c]);
        __nv_bfloat16 ll = __float2bfloat16(v[c] - __bfloat162float(hh));
        ph[c] = __bfloat16_as_ushort(hh);
        pl[c] = __bfloat16_as_ushort(ll);
    }
    size_t base = (size_t)orow * 128 + lane * 4;
    *reinterpret_cast<ushort4*>(oh + base) = sh;
    *reinterpret_cast<ushort4*>(ol + base) = sl;
}

// full aggregation: one warp per node
__global__ __launch_bounds__(256)
void k_agg(const float* __restrict__ x, __nv_bfloat16* __restrict__ oh,
           __nv_bfloat16* __restrict__ ol, int n) {
    int gw   = (blockIdx.x * blockDim.x + threadIdx.x) >> 5;
    int lane = threadIdx.x & 31;
    if (gw >= n) return;
    agg_node(reinterpret_cast<const float4*>(x), gw, lane, oh, ol, gw);
}

// selective aggregation: one warp per needed node (compact output)
__global__ __launch_bounds__(256)
void k_agg_sel(const float* __restrict__ x, __nv_bfloat16* __restrict__ oh,
               __nv_bfloat16* __restrict__ ol) {
    int gw   = (blockIdx.x * blockDim.x + threadIdx.x) >> 5;
    int lane = threadIdx.x & 31;
    if (gw >= g_cnt) return;
    agg_node(reinterpret_cast<const float4*>(x), g_list[gw], lane, oh, ol, gw);
}

// ---------------- bf16x3 tensor-core GEMM via mma.sync ----------------
#define LDS_STRIDE 136
#define TILE_HALFS (128 * LDS_STRIDE)
#define GEMM_SMEM  (4 * TILE_HALFS * 2)

template <bool RELU, bool COMPACT>
__global__ __launch_bounds__(256)
void k_gemm_mma(const __nv_bfloat16* __restrict__ Ah, const __nv_bfloat16* __restrict__ Al,
                const __nv_bfloat16* __restrict__ Bh, const __nv_bfloat16* __restrict__ Bl,
                const float* __restrict__ bias, float* __restrict__ C, int Mfix) {
    const int M = COMPACT ? g_cnt : Mfix;
    const int brow = blockIdx.x * 128;
    if (brow >= M) return;

    extern __shared__ __align__(16) __nv_bfloat16 sm[];
    __nv_bfloat16* sAh = sm;
    __nv_bfloat16* sAl = sAh + TILE_HALFS;
    __nv_bfloat16* sBh = sAl + TILE_HALFS;
    __nv_bfloat16* sBl = sBh + TILE_HALFS;

    const int tid = threadIdx.x, wid = tid >> 5, lane = tid & 31;

    for (int i = tid; i < 2048; i += 256) {
        int r  = i >> 4;
        int c8 = (i & 15) << 3;
        int d  = r * LDS_STRIDE + c8;
        int grow = brow + r;
        uint4 va = make_uint4(0, 0, 0, 0), vl = make_uint4(0, 0, 0, 0);
        if (grow < M) {
            va = *reinterpret_cast<const uint4*>(Ah + (size_t)grow * 128 + c8);
            vl = *reinterpret_cast<const uint4*>(Al + (size_t)grow * 128 + c8);
        }
        *reinterpret_cast<uint4*>(sAh + d) = va;
        *reinterpret_cast<uint4*>(sAl + d) = vl;
        *reinterpret_cast<uint4*>(sBh + d) =
            *reinterpret_cast<const uint4*>(Bh + (size_t)r * 128 + c8);
        *reinterpret_cast<uint4*>(sBl + d) =
            *reinterpret_cast<const uint4*>(Bl + (size_t)r * 128 + c8);
    }
    __syncthreads();

    const int mb = (wid & 3) * 32;
    const int nb = (wid >> 2) * 64;

    float acc[2][8][4];
    #pragma unroll
    for (int i = 0; i < 2; i++)
        #pragma unroll
        for (int j = 0; j < 8; j++)
            #pragma unroll
            for (int q = 0; q < 4; q++) acc[i][j][q] = 0.0f;

    const int lrow  = lane & 15;
    const int lbyte = (lane >> 4) << 4;

    #pragma unroll
    for (int pass = 0; pass < 3; pass++) {
        const __nv_bfloat16* pA = (pass == 1) ? sAl : sAh;
        const __nv_bfloat16* pB = (pass == 2) ? sBl : sBh;
        #pragma unroll
        for (int k16 = 0; k16 < 8; k16++) {
            int kb = k16 * 16;
            uint32_t a[2][4];
            #pragma unroll
            for (int i = 0; i < 2; i++) {
                uint32_t ad = smem_u32(pA + (mb + i * 16 + lrow) * LDS_STRIDE + kb) + lbyte;
                ldsm_x4(ad, a[i][0], a[i][1], a[i][2], a[i][3]);
            }
            uint32_t b[4][4];
            #pragma unroll
            for (int j = 0; j < 4; j++) {
                uint32_t ad = smem_u32(pB + (nb + j * 16 + lrow) * LDS_STRIDE + kb) + lbyte;
                ldsm_x4(ad, b[j][0], b[j][1], b[j][2], b[j][3]);
            }
            #pragma unroll
            for (int i = 0; i < 2; i++)
                #pragma unroll
                for (int j = 0; j < 4; j++) {
                    mma_bf16(acc[i][j * 2 + 0], a[i], b[j][0], b[j][2]);
                    mma_bf16(acc[i][j * 2 + 1], a[i], b[j][1], b[j][3]);
                }
        }
    }

    const int tr = lane >> 2, tc = (lane & 3) * 2;
    #pragma unroll
    for (int i = 0; i < 2; i++) {
        #pragma unroll
        for (int j = 0; j < 8; j++) {
            int col = nb + j * 8 + tc;
            float bx = bias[col], by = bias[col + 1];
            int row0 = brow + mb + i * 16 + tr;
            float2 o0, o1;
            o0.x = acc[i][j][0] + bx; o0.y = acc[i][j][1] + by;
            o1.x = acc[i][j][2] + bx; o1.y = acc[i][j][3] + by;
            if (RELU) {
                o0.x = fmaxf(o0.x, 0.f); o0.y = fmaxf(o0.y, 0.f);
                o1.x = fmaxf(o1.x, 0.f); o1.y = fmaxf(o1.y, 0.f);
            }
            if (row0 < M)
                *reinterpret_cast<float2*>(C + (size_t)row0 * 128 + col) = o0;
            if (row0 + 8 < M)
                *reinterpret_cast<float2*>(C + (size_t)(row0 + 8) * 128 + col) = o1;
        }
    }
}

// ---------------- final gather (z is compact, indexed via g_slot) ----------------
__global__ __launch_bounds__(256)
void k_gather(const float* __restrict__ z, const float* __restrict__ emb,
              const int* __restrict__ seq, float* __restrict__ out, int S) {
    int t = blockIdx.x * blockDim.x + threadIdx.x;
    int pos = t >> 5, lane = t & 31;
    if (pos >= S) return;
    int v = seq[pos];
    const float4* srcp;
    size_t row;
    if (v >= 0) { srcp = reinterpret_cast<const float4*>(z);   row = (size_t)g_slot[v]; }
    else        { srcp = reinterpret_cast<const float4*>(emb); row = (size_t)(v + OFFS + NUM_NODES); }
    reinterpret_cast<float4*>(out)[(size_t)pos * 32 + lane] = srcp[row * 32 + lane];
}

// ---------------- host launch ----------------
extern "C" void kernel_launch(void* const* d_in, const int* in_sizes, int n_in,
                              void* d_out, int out_size) {
    const float* emb = (const float*)d_in[0];
    const float* W0  = (const float*)d_in[1];
    const float* b0  = (const float*)d_in[2];
    const float* W1  = (const float*)d_in[3];
    const float* b1  = (const float*)d_in[4];
    const int*   ei  = (const int*)d_in[5];
    const int*   seq = (const int*)d_in[6];

    int E = in_sizes[5] / 2;
    int S = in_sizes[6];
    const int* src = ei;
    const int* dst = ei + E;

    float *h = nullptr, *z = nullptr;
    __nv_bfloat16 *xh = nullptr, *xl = nullptr, *w0h = nullptr, *w0l = nullptr,
                  *w1h = nullptr, *w1l = nullptr;
    cudaGetSymbolAddress((void**)&h,   g_h);
    cudaGetSymbolAddress((void**)&z,   g_z);
    cudaGetSymbolAddress((void**)&xh,  g_xh);
    cudaGetSymbolAddress((void**)&xl,  g_xl);
    cudaGetSymbolAddress((void**)&w0h, g_w0h);
    cudaGetSymbolAddress((void**)&w0l, g_w0l);
    cudaGetSymbolAddress((void**)&w1h, g_w1h);
    cudaGetSymbolAddress((void**)&w1l, g_w1l);

    cudaFuncSetAttribute((const void*)k_gemm_mma<true, false>,
                         cudaFuncAttributeMaxDynamicSharedMemorySize, GEMM_SMEM);
    cudaFuncSetAttribute((const void*)k_gemm_mma<false, true>,
                         cudaFuncAttributeMaxDynamicSharedMemorySize, GEMM_SMEM);

    const int NBLK = (NUM_NODES + 255) / 256;

    k_init<<<NBLK, 256>>>(W0, W1);
    k_mark<<<(S + 255) / 256, 256>>>(seq, S);
    k_build<<<NBLK, 256>>>();
    k_count<<<(E + 255) / 256, 256>>>(dst, E);
    k_scan_block<<<NBLK, 256>>>(NUM_NODES);
    k_scan_top<<<1, 512>>>(NBLK);
    k_scan_add<<<NBLK, 256>>>(NUM_NODES, E);
    k_fill<<<(E + 255) / 256, 256>>>(src, dst, E);

    const int AGG_GRID   = (NUM_NODES * 32 + 255) / 256;
    const int AGG2_GRID  = (S * 32 + 255) / 256;       // upper bound: S needed nodes
    const int GEMM_GRID  = (NUM_NODES + 127) / 128;
    const int GEMM2_GRID = (S + 127) / 128;

    // layer 1 (all nodes)
    k_agg<<<AGG_GRID, 256>>>(emb, xh, xl, NUM_NODES);
    k_gemm_mma<true, false><<<GEMM_GRID, 256, GEMM_SMEM>>>(xh, xl, w0h, w0l, b0, h, NUM_NODES);
    // layer 2 (needed nodes only, compact)
    k_agg_sel<<<AGG2_GRID, 256>>>(h, xh, xl);
    k_gemm_mma<false, true><<<GEMM2_GRID, 256, GEMM_SMEM>>>(xh, xl, w1h, w1l, b1, z, 0);
    // gather
    k_gather<<<(S * 32 + 255) / 256, 256>>>(z, emb, seq, (float*)d_out, S);
}